// round 3
// baseline (speedup 1.0000x reference)
#include <cuda_runtime.h>

#define C_  512
#define Hh  24
#define Ww  24
#define HW  576
#define NH  8
#define HD  64
#define PW  30
#define PP  900
#define KP  1024          /* padded distinct-key count (power of 2) */
#define SEW 1032          /* sE row stride */

typedef unsigned long long ull;

// Scratch (device globals: allocation-free)
__device__ float g_Xp[C_ * KP];   // reflect-padded x; zeros for pp>=900
__device__ float g_Q [C_ * HW];   // Q[o][p]
__device__ float g_K [C_ * KP];   // K[o][pp]
__device__ float g_VT[KP * C_];   // V transposed: VT[pp][o]

// ---- packed fp32x2 helpers ----
__device__ __forceinline__ void fma2(ull &d, ull a, ull b) {
    asm("fma.rn.f32x2 %0, %1, %2, %0;" : "+l"(d) : "l"(a), "l"(b));
}
__device__ __forceinline__ ull pk2(float x, float y) {
    ull r; asm("mov.b64 %0, {%1, %2};" : "=l"(r) : "f"(x), "f"(y)); return r;
}
__device__ __forceinline__ float2 upk(ull v) {
    float2 r; asm("mov.b64 {%0, %1}, %2;" : "=f"(r.x), "=f"(r.y) : "l"(v)); return r;
}

// ---------------------------------------------------------------------------
// Kernel 1: reflect-pad gather. g_Xp[c][pp] (pp = pr*30+pc), zeros for pp>=900.
// ---------------------------------------------------------------------------
__global__ void pad_kernel(const float* __restrict__ x) {
    int idx = blockIdx.x * 256 + threadIdx.x;
    int c = idx >> 10, pp = idx & (KP - 1);
    float v = 0.f;
    if (pp < PP) {
        int pr = pp / PW, pc = pp - pr * PW;
        int r = pr - 3; r = (r < 0) ? -r : ((r >= Hh) ? 2 * Hh - 2 - r : r);
        int cl = pc - 3; cl = (cl < 0) ? -cl : ((cl >= Ww) ? 2 * Ww - 2 - cl : cl);
        v = x[c * HW + r * Ww + cl];
    }
    g_Xp[idx] = v;
}

// ---------------------------------------------------------------------------
// Kernel 2 (fused): all three conv1x1 GEMMs, 656 CTAs (4-5 per SM).
//   bid [0,144)  : Q  = Wq @ x      (N=576)
//   bid [144,400): K  = Wk @ Xp     (N=1024)
//   bid [400,656): VT = (Wv @ Xp)^T (N=1024, transposed store via smem)
// 32x64 tile, 256 threads, 2x4 micro-tile, double-buffered smem.
// Inner step: LDS.64 + LDS.128 + 2 MOV + 4 FFMA2 = 8 issues (exact floor).
// ---------------------------------------------------------------------------
__global__ void __launch_bounds__(256) gemm_all_kernel(
    const float* __restrict__ Wq, const float* __restrict__ bq,
    const float* __restrict__ Wk, const float* __restrict__ bk,
    const float* __restrict__ Wv, const float* __restrict__ bv,
    const float* __restrict__ x)
{
    __shared__ float sm[3136];  // sA0@0[544] sA1@544[544] sB0@1088[1024] sB1@2112[1024]

    int bid = blockIdx.x;
    const float *Wm, *bias, *X; float* Cout; int N, transp = 0, nt, ot;
    if (bid < 144)      { nt = bid % 9;  ot = bid / 9;  Wm = Wq; bias = bq; X = x;    Cout = g_Q;  N = HW; }
    else if (bid < 400) { int b = bid - 144; nt = b & 15; ot = b >> 4; Wm = Wk; bias = bk; X = g_Xp; Cout = g_K;  N = KP; }
    else                { int b = bid - 400; nt = b & 15; ot = b >> 4; Wm = Wv; bias = bv; X = g_Xp; Cout = g_VT; N = KP; transp = 1; }
    int nB = nt * 64, oB = ot * 32;

    int tid = threadIdx.x;
    int tx = tid & 15, ty = tid >> 4;            // micro-tile: 2 o-rows (2ty), 4 n-cols (4tx)
    // staging indices
    int aoo = tid >> 2, acg = (tid & 3) << 2;    // A: threads<128: o-row, c-group of 4
    int bl = tid >> 4, bn = (tid & 15) << 2;     // B: c-row 0..15, n-group of 4

    float* sA[2] = { sm,        sm + 544  };     // [c][o], stride 34
    float* sB[2] = { sm + 1088, sm + 2112 };     // [c][n], stride 64

    ull a00 = 0, a01 = 0, a10 = 0, a11 = 0;

    // preload chunk 0
    {
        float4 x4 = *(const float4*)&X[bl * N + nB + bn];
        *(float4*)&sB[0][bl * 64 + bn] = x4;
        if (tid < 128) {
            float4 w4 = *(const float4*)&Wm[(oB + aoo) * C_ + acg];
            sA[0][(acg + 0) * 34 + aoo] = w4.x;
            sA[0][(acg + 1) * 34 + aoo] = w4.y;
            sA[0][(acg + 2) * 34 + aoo] = w4.z;
            sA[0][(acg + 3) * 34 + aoo] = w4.w;
        }
    }
    __syncthreads();

    for (int cc = 0; cc < C_; cc += 16) {
        int cur = (cc >> 4) & 1;
        const float* cA = sA[cur];
        const float* cB = sB[cur];
        bool pf = cc + 16 < C_;
        float4 w4n, x4n;
        if (pf) {
            x4n = *(const float4*)&X[(cc + 16 + bl) * N + nB + bn];
            if (tid < 128)
                w4n = *(const float4*)&Wm[(oB + aoo) * C_ + cc + 16 + acg];
        }
#pragma unroll
        for (int t = 0; t < 16; t++) {
            float2 a2 = *(const float2*)&cA[t * 34 + (ty << 1)];
            ulonglong2 b2 = *(const ulonglong2*)&cB[t * 64 + (tx << 2)];
            ull d0 = pk2(a2.x, a2.x), d1 = pk2(a2.y, a2.y);
            fma2(a00, d0, b2.x); fma2(a01, d0, b2.y);
            fma2(a10, d1, b2.x); fma2(a11, d1, b2.y);
        }
        if (pf) {
            float* nA = sA[cur ^ 1];
            float* nBp = sB[cur ^ 1];
            *(float4*)&nBp[bl * 64 + bn] = x4n;
            if (tid < 128) {
                nA[(acg + 0) * 34 + aoo] = w4n.x;
                nA[(acg + 1) * 34 + aoo] = w4n.y;
                nA[(acg + 2) * 34 + aoo] = w4n.z;
                nA[(acg + 3) * 34 + aoo] = w4n.w;
            }
        }
        __syncthreads();
    }

    // epilogue
    float bv0 = bias[oB + (ty << 1)], bv1 = bias[oB + (ty << 1) + 1];
    float2 r00 = upk(a00), r01 = upk(a01), r10 = upk(a10), r11 = upk(a11);
    float4 cv0 = make_float4(r00.x + bv0, r00.y + bv0, r01.x + bv0, r01.y + bv0);
    float4 cv1 = make_float4(r10.x + bv1, r10.y + bv1, r11.x + bv1, r11.y + bv1);
    if (!transp) {
        *(float4*)&Cout[(oB + (ty << 1) + 0) * N + nB + (tx << 2)] = cv0;
        *(float4*)&Cout[(oB + (ty << 1) + 1) * N + nB + (tx << 2)] = cv1;
    } else {
        // transpose through smem (sm reusable: loop ended with __syncthreads)
        float* sT = sm;                          // [n][o], 64 x 33
        float v0[4] = {cv0.x, cv0.y, cv0.z, cv0.w};
        float v1[4] = {cv1.x, cv1.y, cv1.z, cv1.w};
#pragma unroll
        for (int j = 0; j < 4; j++) {
            sT[((tx << 2) + j) * 33 + (ty << 1) + 0] = v0[j];
            sT[((tx << 2) + j) * 33 + (ty << 1) + 1] = v1[j];
        }
        __syncthreads();
#pragma unroll
        for (int it = 0; it < 8; it++) {
            int idx = it * 256 + tid;
            int n = idx >> 5, o = idx & 31;
            Cout[(nB + n) * C_ + oB + o] = sT[n * 33 + o];
        }
    }
}

// ---------------------------------------------------------------------------
// Kernel 3: fused attention, 1024 padded dedup keys, weighted softmax.
// Grid (18 qtiles, 8 heads) = 144 CTAs x 512 threads (16 warps, 4/SMSP).
// 128-key chunks, double-buffered. Full 32x1032 E tile in smem.
// ---------------------------------------------------------------------------
__global__ void __launch_bounds__(512) attn_kernel(const float* __restrict__ x,
                            const float* __restrict__ gamma_p,
                            float* __restrict__ out) {
    extern __shared__ float smd[];
    float* sQ   = smd;                     // 64*32   = 2048 : sQ[d][q]
    float* sKV0 = smd + 2048;              // 8704 (pass1: [64][136] K; pass2: [128][68] V)
    float* sKV1 = sKV0 + 8704;             // 8704
    float* sE   = sKV1 + 8704;             // 32*1032 = 33024
    float* sInv = sE + 32 * SEW;           // 32

    int h   = blockIdx.y;
    int q0  = blockIdx.x * 32;
    int tid = threadIdx.x;
    float* sKVb[2] = { sKV0, sKV1 };

    // ---- Load Q tile (d-major) ----
    {
        int d = tid >> 3, qg = (tid & 7) << 2;
        *(float4*)&sQ[d * 32 + qg] = *(const float4*)&g_Q[(h * HD + d) * HW + q0 + qg];
    }
    // ---- preload K chunk 0: sKV[d][k], stride 136, 64d x 128k ----
    int kd = tid >> 3, kg = (tid & 7) << 4;          // K staging: row d, 16-col group
    {
        const float4* src = (const float4*)&g_K[(h * HD + kd) * KP + kg];
        float4 r0 = src[0], r1 = src[1], r2 = src[2], r3 = src[3];
        float4* dst = (float4*)&sKV0[kd * 136 + kg];
        dst[0] = r0; dst[1] = r1; dst[2] = r2; dst[3] = r3;
    }
    __syncthreads();

    // ---- Pass 1: E[q][k] = sum_d Q[d][q]*K[d][k]. micro 2q x 4k ----
    {
        int tx = tid & 31, ty = tid >> 5;           // k-quad 4tx, q-pair 2ty
        for (int kc = 0; kc < KP; kc += 128) {
            int cur = (kc >> 7) & 1;
            const float* cK = sKVb[cur];
            bool pf = kc + 128 < KP;
            float4 r0, r1, r2, r3;
            if (pf) {
                const float4* src = (const float4*)&g_K[(h * HD + kd) * KP + kc + 128 + kg];
                r0 = src[0]; r1 = src[1]; r2 = src[2]; r3 = src[3];
            }
            ull e00 = 0, e01 = 0, e10 = 0, e11 = 0;
#pragma unroll 16
            for (int d = 0; d < 64; d++) {
                float2 a = *(const float2*)&sQ[d * 32 + (ty << 1)];
                ulonglong2 b = *(const ulonglong2*)&cK[d * 136 + (tx << 2)];
                ull d0 = pk2(a.x, a.x), d1 = pk2(a.y, a.y);
                fma2(e00, d0, b.x); fma2(e01, d0, b.y);
                fma2(e10, d1, b.x); fma2(e11, d1, b.y);
            }
            {
                float2 p0 = upk(e00), p1 = upk(e01), p2 = upk(e10), p3 = upk(e11);
                int r = (ty << 1) * SEW + kc + (tx << 2);
                *(float4*)&sE[r]       = make_float4(p0.x, p0.y, p1.x, p1.y);
                *(float4*)&sE[r + SEW] = make_float4(p2.x, p2.y, p3.x, p3.y);
            }
            if (pf) {
                float4* dst = (float4*)&sKVb[cur ^ 1][kd * 136 + kg];
                dst[0] = r0; dst[1] = r1; dst[2] = r2; dst[3] = r3;
            }
            __syncthreads();
        }
    }

    // ---- issue V chunk-0 loads early (complete under softmax) ----
    int vk = tid >> 2, vg = (tid & 3) << 4;          // V staging: row k, 16-col group
    float4 v0r, v1r, v2r, v3r;
    {
        const float4* src = (const float4*)&g_VT[vk * C_ + h * HD + vg];
        v0r = src[0]; v1r = src[1]; v2r = src[2]; v3r = src[3];
    }

    // ---- Multiplicity-weighted softmax in place: P = mult*exp(E-max) ----
    {
        int row = tid >> 4, part = tid & 15;         // 16 threads per query row
        float* Er = &sE[row * SEW];
        int i0 = part << 6;                          // 64 elems each
        float m = -1e30f;
        for (int i = i0; i < i0 + 64; i++) m = fmaxf(m, Er[i]);
        m = fmaxf(m, __shfl_xor_sync(~0u, m, 1));
        m = fmaxf(m, __shfl_xor_sync(~0u, m, 2));
        m = fmaxf(m, __shfl_xor_sync(~0u, m, 4));
        m = fmaxf(m, __shfl_xor_sync(~0u, m, 8));
        float s = 0.f;
        for (int i = i0; i < i0 + 64; i++) {
            float w = 0.f;
            if (i < PP) {
                int pr = i / PW, pc = i - pr * PW;
                int mr = min(pr + 1, min(7, PW - pr));
                int mc = min(pc + 1, min(7, PW - pc));
                w = (float)(mr * mc);
            }
            float p = w * __expf(Er[i] - m);
            Er[i] = p;
            s += p;
        }
        s += __shfl_xor_sync(~0u, s, 1);
        s += __shfl_xor_sync(~0u, s, 2);
        s += __shfl_xor_sync(~0u, s, 4);
        s += __shfl_xor_sync(~0u, s, 8);
        if (part == 0) sInv[row] = 1.f / s;
    }
    // store V chunk 0: sKV0 as [128][68]
    {
        float4* dst = (float4*)&sKV0[vk * 68 + vg];
        dst[0] = v0r; dst[1] = v1r; dst[2] = v2r; dst[3] = v3r;
    }
    __syncthreads();

    // ---- Pass 2: out[q][d] = sum_k P[q][k]*V[k][d]. micro 1q x 4d, 2k/iter ----
    ull o0 = 0, o1 = 0;
    {
        int tx = tid & 15, ty = tid >> 4;            // d-quad 4tx, q = ty (0..31)
        for (int kc = 0; kc < KP; kc += 128) {
            int cur = (kc >> 7) & 1;
            const float* cV = sKVb[cur];
            bool pf = kc + 128 < KP;
            float4 r0, r1, r2, r3;
            if (pf) {
                const float4* src = (const float4*)&g_VT[(kc + 128 + vk) * C_ + h * HD + vg];
                r0 = src[0]; r1 = src[1]; r2 = src[2]; r3 = src[3];
            }
            const float* Pr = &sE[ty * SEW + kc];
#pragma unroll 8
            for (int k = 0; k < 128; k += 2) {
                float2 p = *(const float2*)&Pr[k];
                ulonglong2 va = *(const ulonglong2*)&cV[k * 68 + (tx << 2)];
                ulonglong2 vb = *(const ulonglong2*)&cV[(k + 1) * 68 + (tx << 2)];
                ull pa = pk2(p.x, p.x), pb = pk2(p.y, p.y);
                fma2(o0, pa, va.x); fma2(o1, pa, va.y);
                fma2(o0, pb, vb.x); fma2(o1, pb, vb.y);
            }
            if (pf) {
                float4* dst = (float4*)&sKVb[cur ^ 1][vk * 68 + vg];
                dst[0] = r0; dst[1] = r1; dst[2] = r2; dst[3] = r3;
            }
            __syncthreads();
        }
    }

    // ---- Epilogue via smem transpose: out = gamma*acc/denom + x ----
    {
        int tx = tid & 15, ty = tid >> 4;
        float2 c0 = upk(o0), c1 = upk(o1);
        float v[4] = {c0.x, c0.y, c1.x, c1.y};
        float* sT = sKV0;                            // 64 x 33 fits in 8704
#pragma unroll
        for (int j = 0; j < 4; j++)
            sT[((tx << 2) + j) * 33 + ty] = v[j];
        __syncthreads();
        float g = *gamma_p;
#pragma unroll
        for (int it = 0; it < 4; it++) {
            int idx = it * 512 + tid;
            int d = idx >> 5, q = idx & 31;
            int gi = (h * HD + d) * HW + q0 + q;
            out[gi] = g * sT[d * 33 + q] * sInv[q] + x[gi];
        }
    }
}

// ---------------------------------------------------------------------------
extern "C" void kernel_launch(void* const* d_in, const int* in_sizes, int n_in,
                              void* d_out, int out_size) {
    const float* x     = (const float*)d_in[0];
    const float* Wq    = (const float*)d_in[1];
    const float* bq    = (const float*)d_in[2];
    const float* Wk    = (const float*)d_in[3];
    const float* bk    = (const float*)d_in[4];
    const float* Wv    = (const float*)d_in[5];
    const float* bv    = (const float*)d_in[6];
    const float* gamma = (const float*)d_in[7];
    float* out = (float*)d_out;

    pad_kernel<<<(C_ * KP) / 256, 256>>>(x);
    gemm_all_kernel<<<656, 256>>>(Wq, bq, Wk, bk, Wv, bv, x);

    const int smem_bytes = (2048 + 2 * 8704 + 32 * SEW + 32) * 4;  // 210048
    cudaFuncSetAttribute(attn_kernel, cudaFuncAttributeMaxDynamicSharedMemorySize, smem_bytes);
    attn_kernel<<<dim3(HW / 32, NH), 512, smem_bytes>>>(x, gamma, out);
}